// round 5
// baseline (speedup 1.0000x reference)
#include <cuda_runtime.h>

#define BB 256
#define TT 2048
#define II 64
#define HH 256

// Persistent scratch for the input projection (zero-init; t>=len region never
// written -> deterministic reads).
__device__ float g_xp[(size_t)BB * TT * HH];

typedef unsigned long long u64;

// ---------------------------------------------------------------------------
// f32x2 packed-math helpers
// ---------------------------------------------------------------------------
__device__ __forceinline__ u64 pack2(float lo, float hi) {
    u64 r; asm("mov.b64 %0, {%1,%2};" : "=l"(r) : "f"(lo), "f"(hi)); return r;
}
__device__ __forceinline__ void ffma2(u64& acc, u64 a, u64 b) {
    asm("fma.rn.f32x2 %0, %1, %2, %0;" : "+l"(acc) : "l"(a), "l"(b));
}
__device__ __forceinline__ u64 add2(u64 a, u64 b) {
    u64 r; asm("add.rn.f32x2 %0, %1, %2;" : "=l"(r) : "l"(a), "l"(b)); return r;
}
__device__ __forceinline__ float2 unpack2(u64 v) {
    float2 f; asm("mov.b64 {%0,%1}, %2;" : "=f"(f.x), "=f"(f.y) : "l"(v)); return f;
}

// ---------------------------------------------------------------------------
// Kernel A: xp[b,t,h] = sum_i x[b,t,i]*W_ih[h,i] + b_ih[h] + b_hh[h], t < len[b]
// f32x2 edition: 32 FFMA2 per (t,h), 2 accumulators.
// ---------------------------------------------------------------------------
__global__ __launch_bounds__(256) void xproj_kernel(
    const float* __restrict__ x,
    const int*   __restrict__ lengths,
    const float* __restrict__ W_ih,
    const float* __restrict__ b_ih,
    const float* __restrict__ b_hh)
{
    extern __shared__ float sm[];
    float* ws = sm;                 // [256][65]
    float* xs = sm + 256 * 65;      // [64][64]

    const int b  = blockIdx.y;
    const int t0 = blockIdx.x * 64;
    const int len = lengths[b];
    if (t0 >= len) return;
    const int tcnt = min(64, len - t0);
    const int tid = threadIdx.x;

    for (int idx = tid; idx < HH * II; idx += 256) {
        int h = idx >> 6, i = idx & 63;
        ws[h * 65 + i] = W_ih[idx];
    }
    const float* xbase = x + ((size_t)b * TT + t0) * II;
    for (int idx = tid; idx < tcnt * II; idx += 256) {
        xs[idx] = xbase[idx];
    }
    __syncthreads();

    const int h = tid;
    u64 wp[II / 2];
#pragma unroll
    for (int q = 0; q < II / 2; q++)
        wp[q] = pack2(ws[h * 65 + 2 * q], ws[h * 65 + 2 * q + 1]);
    const u64 bias0 = pack2(b_ih[h] + b_hh[h], 0.f);

    float* xpb = g_xp + ((size_t)b * TT + t0) * HH + h;

    for (int tt = 0; tt < tcnt; tt++) {
        u64 acc0 = bias0, acc1 = 0ull;
        const ulonglong2* xr = (const ulonglong2*)(xs + tt * II);
#pragma unroll
        for (int q = 0; q < II / 4; q++) {
            ulonglong2 xv = xr[q];               // broadcast LDS.128
            ffma2(acc0, wp[2 * q],     xv.x);
            ffma2(acc1, wp[2 * q + 1], xv.y);
        }
        float2 f0 = unpack2(acc0), f1 = unpack2(acc1);
        xpb[(size_t)tt * HH] = (f0.x + f0.y) + (f1.x + f1.y);
    }
}

// ---------------------------------------------------------------------------
// Kernel B: persistent scan, zero-MOV FFMA2 inner loop (swap-store trick).
// 128 CTAs x 256 threads, 2 batch rows/CTA.
// Thread (c=tid&7, g=tid>>3): k ≡ c (mod 8); owns j in [8g,8g+8).
// h buffer per k: float4 (hb0, hb1, hb1, hb0); one LDS.128 gives the two
// FFMA2 h-operands directly. Accumulators mixed: X_p=(j0·b0, j1·b1),
// Y_p=(j0·b1, j1·b0). Reduce-scatter over 8 c-lanes -> lane c finishes
// j-pair p=c&3 with type (c<4 ? X : Y).
// W rows k<KSM in smem (RS=260 -> conflict-free LDS.128); k>=KSM in regs.
// ---------------------------------------------------------------------------
#define RS 260
#define KSM 72
#define SMI (KSM / 8)            // 9 smem k-iterations
#define RGI ((HH - KSM) / 8)     // 23 register k-iterations

__global__ __launch_bounds__(256, 1) void scan_kernel(
    const float* __restrict__ W_hh,
    const int*   __restrict__ lengths,
    const float* __restrict__ W_fc,
    const float* __restrict__ b_fc,
    float*       __restrict__ out)
{
    extern __shared__ float sm[];
    float* WT_s = sm;                                  // [KSM][RS]
    float4* hb0 = (float4*)(sm + KSM * RS);            // [256] (h0,h1,h1,h0)
    float4* hb1 = hb0 + HH;                            // [256]
    float* hlast = (float*)(hb1 + HH);                 // [2][256]
    float* red   = hlast + 2 * HH;                     // [16]

    const int tid = threadIdx.x;
    const int c = tid & 7;
    const int g = tid >> 3;                            // 0..31
    const int b0 = blockIdx.x * 2, b1 = b0 + 1;
    const int L0 = lengths[b0], L1 = lengths[b1];
    const int Tmax = max(L0, L1);

    // Stage W^T rows k < KSM into smem (coalesced read of W_hh).
    for (int idx = tid; idx < HH * HH; idx += 256) {
        int j = idx >> 8, k = idx & 255;
        float v = W_hh[idx];
        if (k < KSM) WT_s[k * RS + j] = v;
    }
    // Register-resident packed W pairs for k in [KSM, 256), k = KSM + 8*ii + c.
    u64 wpA[RGI], wpB[RGI], wpC[RGI], wpD[RGI];
#pragma unroll
    for (int ii = 0; ii < RGI; ii++) {
        int k = KSM + 8 * ii + c;
        wpA[ii] = pack2(__ldg(&W_hh[(8*g+0)*HH + k]), __ldg(&W_hh[(8*g+1)*HH + k]));
        wpB[ii] = pack2(__ldg(&W_hh[(8*g+2)*HH + k]), __ldg(&W_hh[(8*g+3)*HH + k]));
        wpC[ii] = pack2(__ldg(&W_hh[(8*g+4)*HH + k]), __ldg(&W_hh[(8*g+5)*HH + k]));
        wpD[ii] = pack2(__ldg(&W_hh[(8*g+6)*HH + k]), __ldg(&W_hh[(8*g+7)*HH + k]));
    }
    hb0[tid] = make_float4(0.f, 0.f, 0.f, 0.f);
    hlast[tid] = 0.f; hlast[HH + tid] = 0.f;
    __syncthreads();

    // Per-lane final assignment after reduce-scatter:
    const bool isY = (c & 4) != 0;
    const int p    = c & 3;
    const int j0   = 8 * g + 2 * p;
    const int j1   = j0 + 1;
    const int LA   = isY ? L1 : L0;      // batch of v0 (value at j0)
    const int LB   = isY ? L0 : L1;      // batch of v1 (value at j1)
    const float* xpA = g_xp + (size_t)(isY ? b1 : b0) * TT * HH + j0;
    const float* xpB = g_xp + (size_t)(isY ? b0 : b1) * TT * HH + j1;

    float e0 = xpA[0];                   // xp for t = 0
    float e1 = xpB[0];

    for (int t = 0; t < Tmax; t++) {
        const float4* hcur = (t & 1) ? hb1 : hb0;
        float4*       hnxt = (t & 1) ? hb0 : hb1;
        const ulonglong2* hc2 = (const ulonglong2*)hcur;

        // prefetch xp for t+1 (consumed next iteration; fully hidden)
        int tn = min(t + 1, Tmax - 1);
        float e0n = xpA[(size_t)tn * HH];
        float e1n = xpB[(size_t)tn * HH];

        u64 X0 = 0, X1 = 0, X2 = 0, X3 = 0;   // (j0·b0, j1·b1) per pair
        u64 Y0 = 0, Y1 = 0, Y2 = 0, Y3 = 0;   // (j0·b1, j1·b0)

        // Register-W iterations first (no LSU; overlaps smem load burst).
#pragma unroll
        for (int ii = 0; ii < RGI; ii++) {
            ulonglong2 hv = hc2[KSM + 8 * ii + c];   // .x=(h0,h1) .y=(h1,h0)
            ffma2(X0, wpA[ii], hv.x); ffma2(X1, wpB[ii], hv.x);
            ffma2(X2, wpC[ii], hv.x); ffma2(X3, wpD[ii], hv.x);
            ffma2(Y0, wpA[ii], hv.y); ffma2(Y1, wpB[ii], hv.y);
            ffma2(Y2, wpC[ii], hv.y); ffma2(Y3, wpD[ii], hv.y);
        }
#pragma unroll
        for (int i = 0; i < SMI; i++) {
            int k = 8 * i + c;
            ulonglong2 w01 = *(const ulonglong2*)&WT_s[k * RS + 8 * g];
            ulonglong2 w23 = *(const ulonglong2*)&WT_s[k * RS + 8 * g + 4];
            ulonglong2 hv = hc2[k];
            ffma2(X0, w01.x, hv.x); ffma2(X1, w01.y, hv.x);
            ffma2(X2, w23.x, hv.x); ffma2(X3, w23.y, hv.x);
            ffma2(Y0, w01.x, hv.y); ffma2(Y1, w01.y, hv.y);
            ffma2(Y2, w23.x, hv.y); ffma2(Y3, w23.y, hv.y);
        }

        // Reduce-scatter across the 8 c-lanes.
        u64 A[4] = {X0, X1, X2, X3};
        u64 C4[4] = {Y0, Y1, Y2, Y3};
        u64 R[4];
#pragma unroll
        for (int q = 0; q < 4; q++) {
            u64 keep = isY ? C4[q] : A[q];
            u64 send = isY ? A[q] : C4[q];
            R[q] = add2(keep, __shfl_xor_sync(0xffffffffu, send, 4));
        }
        const bool s2 = (c & 2) != 0;
        u64 S[2];
#pragma unroll
        for (int q = 0; q < 2; q++) {
            u64 keep = s2 ? R[2 + q] : R[q];
            u64 send = s2 ? R[q] : R[2 + q];
            S[q] = add2(keep, __shfl_xor_sync(0xffffffffu, send, 2));
        }
        const bool s3 = (c & 1) != 0;
        u64 keep = s3 ? S[1] : S[0];
        u64 send = s3 ? S[0] : S[1];
        u64 F = add2(keep, __shfl_xor_sync(0xffffffffu, send, 1));

        float2 f = unpack2(F);
        float v0 = tanhf(f.x + e0);      // h_{bA}[j0]
        float v1 = tanhf(f.y + e1);      // h_{bB}[j1]

        // Exchange with partner (c^4) so each lane stores one full float4.
        float r0 = __shfl_xor_sync(0xffffffffu, v0, 4);  // other batch @ j0
        float r1 = __shfl_xor_sync(0xffffffffu, v1, 4);  // other batch @ j1
        // X-lane: hnxt[j0] = (v0, r0, r0, v0); Y-lane: hnxt[j1] = (v1, r1, r1, v1)
        int   jst = isY ? j1 : j0;
        float ss  = isY ? v1 : v0;
        float rr  = isY ? r1 : r0;
        hnxt[jst] = make_float4(ss, rr, rr, ss);

        if (t == LA - 1) hlast[(isY ? 1 : 0) * HH + j0] = v0;
        if (t == LB - 1) hlast[(isY ? 0 : 1) * HH + j1] = v1;

        e0 = e0n; e1 = e1n;
        __syncthreads();   // hnxt visible; fences next-iter writes vs reads
    }

    // Final FC: out[b] = dot(hlast[b], W_fc) + b_fc
    float wf = W_fc[tid];
#pragma unroll
    for (int bb = 0; bb < 2; bb++) {
        float v = hlast[bb * HH + tid] * wf;
#pragma unroll
        for (int o = 16; o > 0; o >>= 1) v += __shfl_down_sync(0xffffffffu, v, o);
        if ((tid & 31) == 0) red[bb * 8 + (tid >> 5)] = v;
    }
    __syncthreads();
    if (tid < 2) {
        float s = b_fc[0];
#pragma unroll
        for (int w = 0; w < 8; w++) s += red[tid * 8 + w];
        out[b0 + tid] = s;
    }
}

// ---------------------------------------------------------------------------
extern "C" void kernel_launch(void* const* d_in, const int* in_sizes, int n_in,
                              void* d_out, int out_size)
{
    const float* x     = (const float*)d_in[0];
    const int*   lens  = (const int*)  d_in[1];
    const float* W_ih  = (const float*)d_in[2];
    const float* W_hh  = (const float*)d_in[3];
    const float* b_ih  = (const float*)d_in[4];
    const float* b_hh  = (const float*)d_in[5];
    const float* W_fc  = (const float*)d_in[6];
    const float* b_fc  = (const float*)d_in[7];
    float* out = (float*)d_out;

    const int A_SMEM = (256 * 65 + 64 * 64) * 4;                          // 82944 B
    const int B_SMEM = KSM * RS * 4 + 2 * HH * 16 + 2 * HH * 4 + 64;      // 85184 B
    cudaFuncSetAttribute(xproj_kernel, cudaFuncAttributeMaxDynamicSharedMemorySize, A_SMEM);
    cudaFuncSetAttribute(scan_kernel,  cudaFuncAttributeMaxDynamicSharedMemorySize, B_SMEM);

    dim3 gA(TT / 64, BB);
    xproj_kernel<<<gA, 256, A_SMEM>>>(x, lens, W_ih, b_ih, b_hh);
    scan_kernel<<<BB / 2, 256, B_SMEM>>>(W_hh, lens, W_fc, b_fc, out);
}